// round 17
// baseline (speedup 1.0000x reference)
#include <cuda_runtime.h>
#include <math.h>

#define FEAT   64
#define EMBC   256
#define IMGSZ  1024
#define NCELLS 256
#define THRESH 0.65f
#define SCAN_BX 8
#define SCAN_BY 111
#define TILE_R  16
#define TILE_C  144
#define YCHUNK  40
#define NSIM    256
#define NINIT   272
#define NBLK    (SCAN_BX * SCAN_BY)

// ---------------- device scratch (no allocations allowed) ----------------
__device__ float d_sim[FEAT * FEAT];
__device__ float d_pdot[2 * FEAT * FEAT];    // per-half partial dots
__device__ float d_pnrm[2 * FEAT * FEAT];    // per-half partial norms
__device__ int   d_hcnt[128];                // per-32px-chunk arrival count (self-reset)
__device__ float4 d_xtab[4096];              // scan x-taps: {i0 (bits), w0, w1, 0}
__device__ float4 d_ytab[4096];              // scan y-taps: {i0 (bits), w0, w1, gy16 (bits)}
__device__ float4 d_xt1[1024];               // 64->1024 taps (P rows AND cols)
__device__ unsigned long long d_minkey;      // global argmin key
__device__ unsigned long long d_cellkey[NCELLS];
__device__ int d_counter = 0;                // scan-done counter (reset by last block)
__device__ int d_go = 0;                     // phase-1-done counter (reset by last block)

// ---------------- ordered-float key helpers ----------------
__device__ __forceinline__ unsigned fkey(float f) {
    unsigned u = __float_as_uint(f);
    return (u >> 31) ? ~u : (u | 0x80000000u);   // monotone: smaller float -> smaller key
}
__device__ __forceinline__ float unfkey(unsigned k) {
    return (k & 0x80000000u) ? __uint_as_float(k & 0x7FFFFFFFu) : __uint_as_float(~k);
}

// ---------------- jax.image.resize (linear, antialias=False) fp-exact taps ----------------
struct Tap { int i0; float w0, w1; };

__device__ __forceinline__ float samplef(int o, float inv) {
    return __fsub_rn(__fmul_rn(__fadd_rn((float)o, 0.5f), inv), 0.5f);
}

__device__ __forceinline__ Tap make_tap(float s, int n) {
    Tap t;
    float fs = floorf(s);
    int i0 = (int)fs;
    if (i0 < 0)            { t.i0 = 0;     t.w0 = 1.f; t.w1 = 0.f; }
    else if (i0 >= n - 1)  { t.i0 = n - 2; t.w0 = 0.f; t.w1 = 1.f; }
    else {
        float w0  = __fsub_rn(1.0f, __fsub_rn(s, fs));
        float w1  = __fsub_rn(1.0f, __fsub_rn((float)(i0 + 1), s));
        float sum = __fadd_rn(w0, w1);
        if (sum != 1.0f) { w0 = __fdiv_rn(w0, sum); w1 = __fdiv_rn(w1, sum); }
        t.i0 = i0; t.w0 = w0; t.w1 = w1;
    }
    return t;
}

// P(r,c) with the exact prep expression (bit-identical wherever computed)
__device__ __forceinline__ float p_val(int pr, int pc) {
    float4 tyr = d_xt1[pr];
    float4 txc = d_xt1[pc];
    int yi = __float_as_int(tyr.x);
    int xi = __float_as_int(txc.x);
    const float* s0 = d_sim + yi * FEAT;
    float cy0 = fmaf(tyr.z, s0[FEAT + xi],     __fmul_rn(tyr.y, s0[xi]));
    float cy1 = fmaf(tyr.z, s0[FEAT + xi + 1], __fmul_rn(tyr.y, s0[xi + 1]));
    return fmaf(txc.z, cy1, __fmul_rn(txc.y, cy0));
}

// ---------------- single fused kernel ----------------
__global__ void __launch_bounds__(256, 6) k_all(const float* __restrict__ emb,
                                                const float* __restrict__ ref,
                                                const int* __restrict__ ori,
                                                float* __restrict__ out) {
    __shared__ float2 tile2[TILE_R][TILE_C];   // {P(r,c), P(r,c+1)} pairs
    __shared__ float4 s_yt[YCHUNK];            // staged y-taps for this strip
    __shared__ float  sph1[768];               // phase-1 scratch (sref/sdot/snrm)
    __shared__ int    s_sec;
    __shared__ int    s_thr;                   // block threshold flag

    int t   = threadIdx.x;
    int bid = blockIdx.y * gridDim.x + blockIdx.x;   // 0..887

    // ================= phase 1 =================
    if (bid < NSIM) {
        // sim: 256 blocks, each = one channel-half (128 ch) of one 32-px chunk
        int half = bid >> 7;          // 0 or 1
        int pxb  = bid & 127;         // 32-px chunk
        float* sref = sph1;
        float* sdot = sph1 + 256;
        float* snrm = sph1 + 512;
        if (t < 128) sref[t] = ref[half * 128 + t];
        __syncthreads();

        int px = (pxb << 5) + (t & 31);
        int q  = t >> 5;              // 0..7, 16 channels each
        const float* e = emb + (half * 128 + q * 16) * (FEAT * FEAT) + px;
        const float* r = sref + q * 16;
        float dot = 0.f, nrm = 0.f;
        #pragma unroll
        for (int j = 0; j < 16; j++) {
            float v = e[j * (FEAT * FEAT)];
            dot = fmaf(r[j], v, dot);
            nrm = fmaf(v, v, nrm);
        }
        sdot[t] = dot; snrm[t] = nrm;
        __syncthreads();

        if (t < 32) {
            float D = sdot[t], N = snrm[t];
            #pragma unroll
            for (int q2 = 1; q2 < 8; q2++) {    // fixed order (deterministic)
                D += sdot[t + (q2 << 5)];
                N += snrm[t + (q2 << 5)];
            }
            int gpx = (pxb << 5) + t;
            d_pdot[half * (FEAT * FEAT) + gpx] = D;
            d_pnrm[half * (FEAT * FEAT) + gpx] = N;
            __threadfence();                    // publish partials
        }
        __syncthreads();
        if (t == 0) s_sec = atomicAdd(&d_hcnt[pxb], 1);
        __syncthreads();
        if (s_sec == 1) {                       // second arrival combines (fixed order)
            __threadfence();                    // acquire partials
            if (t < 32) {
                int gpx = (pxb << 5) + t;
                float D = d_pdot[gpx] + d_pdot[(FEAT * FEAT) + gpx];
                float N = d_pnrm[gpx] + d_pnrm[(FEAT * FEAT) + gpx];
                d_sim[gpx] = D / sqrtf(N);
            }
            if (t == 0) d_hcnt[pxb] = 0;        // reset for next replay
        }
    } else if (bid < NINIT) {
        int idx = (bid - NSIM) * 256 + t;       // 0..4095
        if (idx == 0) d_minkey = ~0ull;
        if (idx < NCELLS) d_cellkey[idx] = 0ull;

        if (idx < 1024) {                       // 64 -> 1024 taps
            Tap tp = make_tap(samplef(idx, 0.0625f), FEAT);
            d_xt1[idx] = make_float4(__int_as_float(tp.i0), tp.w0, tp.w1, 0.f);
        }
        int H = ori[0], W = ori[1];
        int mxv = max(H, W);
        double scale = (double)IMGSZ / (double)mxv;
        int ph = (int)floor((double)H * scale + 0.5);
        int pw = (int)floor((double)W * scale + 0.5);
        float invx = (float)(1.0 / ((double)W / (double)pw));
        float invy = (float)(1.0 / ((double)H / (double)ph));
        float r64  = (float)(scale / 64.0);
        if (idx < W) {
            Tap tp = make_tap(samplef(idx, invx), pw);
            d_xtab[idx] = make_float4(__int_as_float(tp.i0), tp.w0, tp.w1, 0.f);
        }
        if (idx < H) {
            Tap tp = make_tap(samplef(idx, invy), ph);
            int gy16 = 16 * (int)floorf(__fmul_rn((float)idx, r64));
            d_ytab[idx] = make_float4(__int_as_float(tp.i0), tp.w0, tp.w1,
                                      __int_as_float(gy16));
        }
    }

    // grid-internal barrier. Phase-1 blocks (bid<272) are wave-1 residents, so
    // d_go always reaches NINIT; later-wave blocks (if any) just see it done.
    if (t == 0) {
        if (bid < NINIT) { __threadfence(); atomicAdd(&d_go, 1); }
        while (*(volatile int*)&d_go < NINIT) __nanosleep(64);
    }
    __syncthreads();

    // ================= phase 2: 2-column tiled scan =================
    int H = ori[0], W = ori[1];
    int mxv = max(H, W);
    double scale = (double)IMGSZ / (double)mxv;
    float r64  = (float)(scale / 64.0);

    int xs = blockIdx.x * 512;
    int nby = gridDim.y;
    int chn = (H + nby - 1) / nby;             // <= YCHUNK
    int ys = blockIdx.y * chn;
    int ye = min(H, ys + chn);

    unsigned long long localkey = ~0ull;

    if (ys < H && xs < W) {
        int ny = ye - ys;
        int xe = min(xs + 512, W);
        int pr0 = __float_as_int(d_ytab[ys].x);
        int pr1 = __float_as_int(d_ytab[ye - 1].x) + 1;
        int px0 = __float_as_int(d_xtab[xs].x);
        int px1 = __float_as_int(d_xtab[xe - 1].x) + 1;
        int NR = pr1 - pr0 + 1;
        int NC = px1 - px0 + 1;

        for (int i = t; i < ny; i += 256) s_yt[i] = d_ytab[ys + i];

        // build tile2 + per-thread max of tile values
        float bmax = -INFINITY;
        int nbuild = NR * (NC - 1);
        for (int i = t; i < nbuild; i += 256) {
            int r = i / (NC - 1), c = i - r * (NC - 1);
            float v0 = p_val(pr0 + r, px0 + c);
            float v1 = p_val(pr0 + r, px0 + c + 1);
            tile2[r][c] = make_float2(v0, v1);
            bmax = fmaxf(bmax, fmaxf(v0, v1));
        }
        // block max of tile values -> threshold flag.
        // Any pixel v is a rounded bilinear of 4 tile values (6 monotone rounded
        // ops) => v <= tile_max + <=8 ulp. Margin 256 key-ulps is safely larger,
        // so s_thr==0 proves no pixel can exceed THRESH.
        __shared__ unsigned long long sk[256];
        sk[t] = fkey(bmax);
        __syncthreads();
        for (int o = 128; o > 0; o >>= 1) {
            if (t < o) sk[t] = max(sk[t], sk[t + o]);
            __syncthreads();
        }
        if (t == 0) s_thr = ((unsigned)sk[0] + 256u >= fkey(THRESH));
        __syncthreads();

        int xa = xs + t;            // column A
        int xb = xa + 256;          // column B
        bool hasB = (xb < W);
        if (xa < W) {
            float4 txA = d_xtab[xa];
            int   lxa  = __float_as_int(txA.x) - px0;
            float wa0 = txA.y, wa1 = txA.z;
            float4 txB = hasB ? d_xtab[xb] : txA;
            int   lxb  = __float_as_int(txB.x) - px0;
            float wb0 = txB.y, wb1 = txB.z;

            // 2 index-tracked chains per column (even/odd y); no max tracking
            float rba0 = INFINITY, rba1 = INFINITY, rbb0 = INFINITY, rbb1 = INFINITY;
            int   ria0 = 0, ria1 = 0, rib0 = 0, rib1 = 0;

            int idx0 = ys * W + xa;
            int i = 0;
            for (; i + 1 < ny; i += 2) {
                #pragma unroll
                for (int j = 0; j < 2; j++) {
                    float4 ty = s_yt[i + j];
                    int lr = __float_as_int(ty.x) - pr0;
                    const float2* R0 = &tile2[lr][0];
                    const float2* R1 = &tile2[lr + 1][0];
                    float2 A0 = R0[lxa], B0 = R1[lxa];
                    float2 A1 = R0[lxb], B1 = R1[lxb];

                    float ca0 = fmaf(ty.z, B0.x, __fmul_rn(ty.y, A0.x));
                    float ca1 = fmaf(ty.z, B0.y, __fmul_rn(ty.y, A0.y));
                    float va  = fmaf(wa1, ca1, __fmul_rn(wa0, ca0));

                    float cb0 = fmaf(ty.z, B1.x, __fmul_rn(ty.y, A1.x));
                    float cb1 = fmaf(ty.z, B1.y, __fmul_rn(ty.y, A1.y));
                    float vb  = fmaf(wb1, cb1, __fmul_rn(wb0, cb0));

                    int idx = idx0 + j * W;
                    if (j == 0) {
                        if (va < rba0) { rba0 = va; ria0 = idx; }
                        if (vb < rbb0) { rbb0 = vb; rib0 = idx; }
                    } else {
                        if (va < rba1) { rba1 = va; ria1 = idx; }
                        if (vb < rbb1) { rbb1 = vb; rib1 = idx; }
                    }
                }
                idx0 += 2 * W;
            }
            for (; i < ny; i++) {                // remainder -> chain 0
                float4 ty = s_yt[i];
                int lr = __float_as_int(ty.x) - pr0;
                const float2* R0 = &tile2[lr][0];
                const float2* R1 = &tile2[lr + 1][0];
                float2 A0 = R0[lxa], B0 = R1[lxa];
                float2 A1 = R0[lxb], B1 = R1[lxb];
                float ca0 = fmaf(ty.z, B0.x, __fmul_rn(ty.y, A0.x));
                float ca1 = fmaf(ty.z, B0.y, __fmul_rn(ty.y, A0.y));
                float va  = fmaf(wa1, ca1, __fmul_rn(wa0, ca0));
                float cb0 = fmaf(ty.z, B1.x, __fmul_rn(ty.y, A1.x));
                float cb1 = fmaf(ty.z, B1.y, __fmul_rn(ty.y, A1.y));
                float vb  = fmaf(wb1, cb1, __fmul_rn(wb0, cb0));
                if (va < rba0) { rba0 = va; ria0 = idx0; }
                if (vb < rbb0) { rbb0 = vb; rib0 = idx0; }
                idx0 += W;
            }

            unsigned long long ka0 = ((unsigned long long)fkey(rba0) << 32) | (unsigned)ria0;
            unsigned long long ka1 = ((unsigned long long)fkey(rba1) << 32) | (unsigned)ria1;
            localkey = min(ka0, ka1);
            if (hasB) {
                unsigned long long kb0 = ((unsigned long long)fkey(rbb0) << 32) | (unsigned)(rib0 + 256);
                unsigned long long kb1 = ((unsigned long long)fkey(rbb1) << 32) | (unsigned)(rib1 + 256);
                localkey = min(localkey, min(kb0, kb1));
            }

            // rare slow path (block-level trigger): identical values & atomics
            if (s_thr) {
                int gxa = (int)floorf(__fmul_rn((float)xa, r64));
                int gxb = (int)floorf(__fmul_rn((float)xb, r64));
                int idx = ys * W + xa;
                for (int k = 0; k < ny; k++) {
                    float4 ty = s_yt[k];
                    int lr = __float_as_int(ty.x) - pr0;
                    const float2* R0 = &tile2[lr][0];
                    const float2* R1 = &tile2[lr + 1][0];
                    float2 A0 = R0[lxa], B0 = R1[lxa];
                    float ca0 = fmaf(ty.z, B0.x, __fmul_rn(ty.y, A0.x));
                    float ca1 = fmaf(ty.z, B0.y, __fmul_rn(ty.y, A0.y));
                    float va  = fmaf(wa1, ca1, __fmul_rn(wa0, ca0));
                    if (va > THRESH) {
                        int cell = __float_as_int(ty.w) + gxa;
                        unsigned long long ck = ((unsigned long long)fkey(va) << 32)
                                              | (unsigned)(0xFFFFFFFFu - (unsigned)idx);
                        atomicMax(&d_cellkey[cell], ck);
                    }
                    if (hasB) {
                        float2 A1 = R0[lxb], B1 = R1[lxb];
                        float cb0 = fmaf(ty.z, B1.x, __fmul_rn(ty.y, A1.x));
                        float cb1 = fmaf(ty.z, B1.y, __fmul_rn(ty.y, A1.y));
                        float vb  = fmaf(wb1, cb1, __fmul_rn(wb0, cb0));
                        if (vb > THRESH) {
                            int cell = __float_as_int(ty.w) + gxb;
                            unsigned long long ck = ((unsigned long long)fkey(vb) << 32)
                                                  | (unsigned)(0xFFFFFFFFu - (unsigned)(idx + 256));
                            atomicMax(&d_cellkey[cell], ck);
                        }
                    }
                    idx += W;
                }
            }
        }
    }

    // block argmin reduction
    __shared__ unsigned long long sk2[256];
    __shared__ int s_last;
    sk2[t] = localkey;
    __syncthreads();
    for (int o = 128; o > 0; o >>= 1) {
        if (t < o) sk2[t] = min(sk2[t], sk2[t + o]);
        __syncthreads();
    }
    if (t == 0) {
        atomicMin(&d_minkey, sk2[0]);
        __threadfence();
        s_last = (atomicAdd(&d_counter, 1) == NBLK - 1);
    }
    __syncthreads();
    if (!s_last) return;

    // ---- last block: finalize + reset cross-launch state ----
    __shared__ float s_key[NCELLS];
    unsigned long long ck = atomicOr(&d_cellkey[t], 0ull);
    bool valid = (ck != 0ull);
    float ps = 0.f; int pidx = 0;
    if (valid) {
        ps   = unfkey((unsigned)(ck >> 32));
        pidx = (int)(0xFFFFFFFFu - (unsigned)(ck & 0xFFFFFFFFull));
    }
    float skey = valid ? ps : -INFINITY;
    s_key[t] = skey;
    __syncthreads();

    int rank = 0;
    #pragma unroll 8
    for (int j = 0; j < NCELLS; j++) {
        float o = s_key[j];
        rank += (o > skey) || (o == skey && j < t);
    }

    out[rank * 3 + 0] = valid ? (float)(pidx % W) : -1.f;
    out[rank * 3 + 1] = valid ? (float)(pidx / W) : -1.f;
    out[rank * 3 + 2] = valid ? ps : -1.f;

    if (t == 0) {
        unsigned long long mk = atomicOr(&d_minkey, 0ull);
        unsigned bidx = (unsigned)(mk & 0xFFFFFFFFull);
        out[NCELLS * 3 + 0] = (float)(bidx % (unsigned)W);   // bg col (x)
        out[NCELLS * 3 + 1] = (float)(bidx / (unsigned)W);   // bg row (y)
        d_go = 0;
        d_counter = 0;
    }
}

// ---------------- launch ----------------
extern "C" void kernel_launch(void* const* d_in, const int* in_sizes, int n_in,
                              void* d_out, int out_size) {
    int ie = 0, ir = 1, io = 2;
    for (int i = 0; i < n_in; i++) {
        if (in_sizes[i] == 2) io = i;
        else if (in_sizes[i] == EMBC) ir = i;
        else ie = i;
    }
    const float* emb = (const float*)d_in[ie];
    const float* ref = (const float*)d_in[ir];
    const int*   ori = (const int*)d_in[io];
    float* out = (float*)d_out;

    k_all<<<dim3(SCAN_BX, SCAN_BY), 256>>>(emb, ref, ori, out);
}